// round 3
// baseline (speedup 1.0000x reference)
#include <cuda_runtime.h>

#define N_NODES 50000
#define E_EDGES 800000
#define INF_    256
#define OUTF_   32
#define HEADS_  8
#define HF_     256   // HEADS_ * OUTF_

// ---------------- scratch (static __device__, no allocation) ----------------
__device__ float g_Wt[INF_ * HF_];                       // 256 KB packed weights [k][head*32+f]
__device__ float g_h[(size_t)N_NODES * HF_];             // 51.2 MB transformed features
__device__ float g_ssrc[N_NODES * HEADS_];               // 1.6 MB
__device__ float g_sdst[N_NODES * HEADS_];               // 1.6 MB
__device__ int   g_deg[N_NODES];
__device__ int   g_cursor[N_NODES];
__device__ int   g_rowstart[N_NODES + 1];
__device__ int   g_csr_src[E_EDGES];                     // 3.2 MB src per CSR slot

// ---------------- pack W [H,256,32] -> Wt [256, 256] ------------------------
__global__ void k_pack(const float* __restrict__ W) {
    int idx = blockIdx.x * blockDim.x + threadIdx.x;     // idx = k*256 + j
    if (idx >= INF_ * HF_) return;
    int k = idx >> 8;
    int j = idx & 255;
    int head = j >> 5;
    int f = j & 31;
    g_Wt[idx] = W[head * (INF_ * OUTF_) + k * OUTF_ + f];
}

// ---------------- GEMM: g_h[M,256] = x[M,256] @ g_Wt[256,256] ----------------
// BM=128, BN=64, BK=16, 256 threads, 8x4 micro-tile per thread.
__global__ void k_gemm(const float* __restrict__ x, int M) {
    __shared__ float As[16][128];
    __shared__ float Bs[16][64];
    const int tid = threadIdx.x;
    const int tx = tid & 15;        // col group (0..15) -> cols tx*4
    const int ty = tid >> 4;        // row group (0..15) -> rows ty*8
    const int n0 = blockIdx.x * 64;
    const int m0 = blockIdx.y * 128;

    float acc[8][4];
#pragma unroll
    for (int i = 0; i < 8; i++)
#pragma unroll
        for (int j = 0; j < 4; j++) acc[i][j] = 0.f;

    for (int k0 = 0; k0 < INF_; k0 += 16) {
        // load A tile 128x16 (transposed into As[k][m])
#pragma unroll
        for (int i = 0; i < 2; i++) {
            int id = tid + i * 256;          // 0..511 float4 slots
            int row = id >> 2;               // 0..127
            int c4 = id & 3;                 // 0..3
            float4 v = make_float4(0.f, 0.f, 0.f, 0.f);
            if (m0 + row < M)
                v = *(const float4*)&x[(size_t)(m0 + row) * INF_ + k0 + c4 * 4];
            As[c4 * 4 + 0][row] = v.x;
            As[c4 * 4 + 1][row] = v.y;
            As[c4 * 4 + 2][row] = v.z;
            As[c4 * 4 + 3][row] = v.w;
        }
        // load B tile 16x64
        {
            int row = tid >> 4;              // 0..15
            int c4 = tid & 15;               // 0..15
            *(float4*)&Bs[row][c4 * 4] =
                *(const float4*)&g_Wt[(k0 + row) * HF_ + n0 + c4 * 4];
        }
        __syncthreads();

#pragma unroll
        for (int k = 0; k < 16; k++) {
            float4 a0 = *(const float4*)&As[k][ty * 8];
            float4 a1 = *(const float4*)&As[k][ty * 8 + 4];
            float4 b = *(const float4*)&Bs[k][tx * 4];
            float av[8] = {a0.x, a0.y, a0.z, a0.w, a1.x, a1.y, a1.z, a1.w};
            float bv[4] = {b.x, b.y, b.z, b.w};
#pragma unroll
            for (int i = 0; i < 8; i++)
#pragma unroll
                for (int j = 0; j < 4; j++)
                    acc[i][j] = fmaf(av[i], bv[j], acc[i][j]);
        }
        __syncthreads();
    }

#pragma unroll
    for (int i = 0; i < 8; i++) {
        int row = m0 + ty * 8 + i;
        if (row < M) {
            float4 v = make_float4(acc[i][0], acc[i][1], acc[i][2], acc[i][3]);
            *(float4*)&g_h[(size_t)row * HF_ + n0 + tx * 4] = v;
        }
    }
}

// ---------------- per-(node,head) attention logits ---------------------------
__global__ void k_scores(const float* __restrict__ a_src,
                         const float* __restrict__ a_dst, int NN) {
    int t = blockIdx.x * blockDim.x + threadIdx.x;       // t = n*8 + head
    if (t >= NN * HEADS_) return;
    int n = t >> 3;
    int head = t & 7;
    const float4* hv = (const float4*)&g_h[(size_t)n * HF_ + head * OUTF_];
    const float4* sv = (const float4*)&a_src[head * OUTF_];
    const float4* dv = (const float4*)&a_dst[head * OUTF_];
    float ss = 0.f, sd = 0.f;
#pragma unroll
    for (int i = 0; i < 8; i++) {
        float4 h4 = hv[i], s4 = sv[i], d4 = dv[i];
        ss += h4.x * s4.x + h4.y * s4.y + h4.z * s4.z + h4.w * s4.w;
        sd += h4.x * d4.x + h4.y * d4.y + h4.z * d4.z + h4.w * d4.w;
    }
    g_ssrc[t] = ss;
    g_sdst[t] = sd;
}

// ---------------- CSR build --------------------------------------------------
__global__ void k_zero(int NN) {
    int t = blockIdx.x * blockDim.x + threadIdx.x;
    if (t < NN) { g_deg[t] = 0; g_cursor[t] = 0; }
}

__global__ void k_count(const int* __restrict__ dst, int E) {
    int e = blockIdx.x * blockDim.x + threadIdx.x;
    if (e < E) atomicAdd(&g_deg[dst[e]], 1);
}

__global__ void k_scan(int NN) {
    __shared__ int sh[1024];
    __shared__ int carry;
    int tid = threadIdx.x;
    if (tid == 0) carry = 0;
    __syncthreads();
    for (int base = 0; base < NN; base += 1024) {
        int v = (base + tid < NN) ? g_deg[base + tid] : 0;
        sh[tid] = v;
        __syncthreads();
        for (int off = 1; off < 1024; off <<= 1) {
            int t = (tid >= off) ? sh[tid - off] : 0;
            __syncthreads();
            sh[tid] += t;
            __syncthreads();
        }
        if (base + tid < NN) g_rowstart[base + tid] = carry + sh[tid] - v;
        int bs = sh[1023];
        __syncthreads();
        if (tid == 0) carry += bs;
        __syncthreads();
    }
    if (tid == 0) g_rowstart[NN] = carry;
}

__global__ void k_fill(const int* __restrict__ src, const int* __restrict__ dst, int E) {
    int e = blockIdx.x * blockDim.x + threadIdx.x;
    if (e >= E) return;
    int d = dst[e];
    int pos = atomicAdd(&g_cursor[d], 1);
    g_csr_src[g_rowstart[d] + pos] = src[e];
}

// ---------------- fused softmax + aggregation --------------------------------
// block per node (256 threads), warp per head, lane per output feature.
__global__ void k_aggr(float* __restrict__ out) {
    int n = blockIdx.x;
    int head = threadIdx.x >> 5;
    int lane = threadIdx.x & 31;
    __shared__ int s_rs, s_re;
    if (threadIdx.x == 0) {
        s_rs = g_rowstart[n];
        s_re = g_rowstart[n + 1];
    }
    __syncthreads();
    const int rs = s_rs, re = s_re;
    const float sd = g_sdst[n * HEADS_ + head];

    // phase 1: online softmax (max + sum) over incoming edges, lanes strided
    float m = -1e30f, ssum = 0.f;
    for (int i = rs + lane; i < re; i += 32) {
        int s = g_csr_src[i];
        float ea = g_ssrc[s * HEADS_ + head] + sd;
        ea = ea > 0.f ? ea : 0.2f * ea;
        if (ea > m) { ssum *= __expf(m - ea); m = ea; }
        ssum += __expf(ea - m);
    }
#pragma unroll
    for (int off = 16; off; off >>= 1) {
        float m2 = __shfl_xor_sync(0xffffffffu, m, off);
        float s2 = __shfl_xor_sync(0xffffffffu, ssum, off);
        float mn = fmaxf(m, m2);
        ssum = ssum * __expf(m - mn) + s2 * __expf(m2 - mn);
        m = mn;
    }
    float inv = 1.0f / (ssum + 1e-8f);

    // phase 2: weighted gather; coef recomputed per edge (broadcast loads),
    // each lane accumulates one output feature.
    float acc = 0.f;
    for (int i = rs; i < re; i++) {
        int s = g_csr_src[i];
        float ea = g_ssrc[s * HEADS_ + head] + sd;
        ea = ea > 0.f ? ea : 0.2f * ea;
        float c = __expf(ea - m) * inv;
        acc = fmaf(c, g_h[(size_t)s * HF_ + head * OUTF_ + lane], acc);
    }
    out[(size_t)n * HF_ + head * OUTF_ + lane] = acc;
}

// ---------------- launch -----------------------------------------------------
extern "C" void kernel_launch(void* const* d_in, const int* in_sizes, int n_in,
                              void* d_out, int out_size) {
    const float* x     = (const float*)d_in[0];
    const int*   ei    = (const int*)d_in[1];
    const float* W     = (const float*)d_in[2];
    const float* a_src = (const float*)d_in[3];
    const float* a_dst = (const float*)d_in[4];
    float* out = (float*)d_out;

    const int M = in_sizes[0] / INF_;     // 50000
    const int E = in_sizes[1] / 2;        // 800000
    const int* src = ei;
    const int* dst = ei + E;

    k_pack<<<(INF_ * HF_ + 255) / 256, 256>>>(W);
    k_gemm<<<dim3(HF_ / 64, (M + 127) / 128), 256>>>(x, M);
    k_scores<<<(M * HEADS_ + 255) / 256, 256>>>(a_src, a_dst, M);
    k_zero<<<(M + 255) / 256, 256>>>(M);
    k_count<<<(E + 255) / 256, 256>>>(dst, E);
    k_scan<<<1, 1024>>>(M);
    k_fill<<<(E + 255) / 256, 256>>>(src, dst, E);
    k_aggr<<<M, 256>>>(out);
}

// round 4
// speedup vs baseline: 1.0006x; 1.0006x over previous
#include <cuda_runtime.h>

#define N_NODES 50000
#define E_EDGES 800000
#define INF_    256
#define OUTF_   32
#define HEADS_  8
#define HF_     256   // HEADS_ * OUTF_

// ---------------- scratch (static __device__, no allocation) ----------------
__device__ float g_Wt[INF_ * HF_];                       // 256 KB packed weights [k][head*32+f]
__device__ float g_h[(size_t)N_NODES * HF_];             // 51.2 MB transformed features
__device__ float g_ssrc[N_NODES * HEADS_];               // 1.6 MB
__device__ float g_sdst[N_NODES * HEADS_];               // 1.6 MB
__device__ int   g_deg[N_NODES];
__device__ int   g_cursor[N_NODES];
__device__ int   g_rowstart[N_NODES + 1];
__device__ int   g_csr_src[E_EDGES];                     // 3.2 MB src per CSR slot

// ---------------- pack W [H,256,32] -> Wt [256, 256] ------------------------
__global__ void k_pack(const float* __restrict__ W) {
    int idx = blockIdx.x * blockDim.x + threadIdx.x;     // idx = k*256 + j
    if (idx >= INF_ * HF_) return;
    int k = idx >> 8;
    int j = idx & 255;
    int head = j >> 5;
    int f = j & 31;
    g_Wt[idx] = W[head * (INF_ * OUTF_) + k * OUTF_ + f];
}

// ---------------- GEMM: g_h[M,256] = x[M,256] @ g_Wt[256,256] ----------------
// BM=128, BN=64, BK=16, 256 threads, 8x4 micro-tile per thread.
__global__ void k_gemm(const float* __restrict__ x, int M) {
    __shared__ float As[16][128];
    __shared__ float Bs[16][64];
    const int tid = threadIdx.x;
    const int tx = tid & 15;        // col group (0..15) -> cols tx*4
    const int ty = tid >> 4;        // row group (0..15) -> rows ty*8
    const int n0 = blockIdx.x * 64;
    const int m0 = blockIdx.y * 128;

    float acc[8][4];
#pragma unroll
    for (int i = 0; i < 8; i++)
#pragma unroll
        for (int j = 0; j < 4; j++) acc[i][j] = 0.f;

    for (int k0 = 0; k0 < INF_; k0 += 16) {
        // load A tile 128x16 (transposed into As[k][m])
#pragma unroll
        for (int i = 0; i < 2; i++) {
            int id = tid + i * 256;          // 0..511 float4 slots
            int row = id >> 2;               // 0..127
            int c4 = id & 3;                 // 0..3
            float4 v = make_float4(0.f, 0.f, 0.f, 0.f);
            if (m0 + row < M)
                v = *(const float4*)&x[(size_t)(m0 + row) * INF_ + k0 + c4 * 4];
            As[c4 * 4 + 0][row] = v.x;
            As[c4 * 4 + 1][row] = v.y;
            As[c4 * 4 + 2][row] = v.z;
            As[c4 * 4 + 3][row] = v.w;
        }
        // load B tile 16x64
        {
            int row = tid >> 4;              // 0..15
            int c4 = tid & 15;               // 0..15
            *(float4*)&Bs[row][c4 * 4] =
                *(const float4*)&g_Wt[(k0 + row) * HF_ + n0 + c4 * 4];
        }
        __syncthreads();

#pragma unroll
        for (int k = 0; k < 16; k++) {
            float4 a0 = *(const float4*)&As[k][ty * 8];
            float4 a1 = *(const float4*)&As[k][ty * 8 + 4];
            float4 b = *(const float4*)&Bs[k][tx * 4];
            float av[8] = {a0.x, a0.y, a0.z, a0.w, a1.x, a1.y, a1.z, a1.w};
            float bv[4] = {b.x, b.y, b.z, b.w};
#pragma unroll
            for (int i = 0; i < 8; i++)
#pragma unroll
                for (int j = 0; j < 4; j++)
                    acc[i][j] = fmaf(av[i], bv[j], acc[i][j]);
        }
        __syncthreads();
    }

#pragma unroll
    for (int i = 0; i < 8; i++) {
        int row = m0 + ty * 8 + i;
        if (row < M) {
            float4 v = make_float4(acc[i][0], acc[i][1], acc[i][2], acc[i][3]);
            *(float4*)&g_h[(size_t)row * HF_ + n0 + tx * 4] = v;
        }
    }
}

// ---------------- per-(node,head) attention logits ---------------------------
__global__ void k_scores(const float* __restrict__ a_src,
                         const float* __restrict__ a_dst, int NN) {
    int t = blockIdx.x * blockDim.x + threadIdx.x;       // t = n*8 + head
    if (t >= NN * HEADS_) return;
    int n = t >> 3;
    int head = t & 7;
    const float4* hv = (const float4*)&g_h[(size_t)n * HF_ + head * OUTF_];
    const float4* sv = (const float4*)&a_src[head * OUTF_];
    const float4* dv = (const float4*)&a_dst[head * OUTF_];
    float ss = 0.f, sd = 0.f;
#pragma unroll
    for (int i = 0; i < 8; i++) {
        float4 h4 = hv[i], s4 = sv[i], d4 = dv[i];
        ss += h4.x * s4.x + h4.y * s4.y + h4.z * s4.z + h4.w * s4.w;
        sd += h4.x * d4.x + h4.y * d4.y + h4.z * d4.z + h4.w * d4.w;
    }
    g_ssrc[t] = ss;
    g_sdst[t] = sd;
}

// ---------------- CSR build --------------------------------------------------
__global__ void k_zero(int NN) {
    int t = blockIdx.x * blockDim.x + threadIdx.x;
    if (t < NN) { g_deg[t] = 0; g_cursor[t] = 0; }
}

__global__ void k_count(const int* __restrict__ dst, int E) {
    int e = blockIdx.x * blockDim.x + threadIdx.x;
    if (e < E) atomicAdd(&g_deg[dst[e]], 1);
}

__global__ void k_scan(int NN) {
    __shared__ int sh[1024];
    __shared__ int carry;
    int tid = threadIdx.x;
    if (tid == 0) carry = 0;
    __syncthreads();
    for (int base = 0; base < NN; base += 1024) {
        int v = (base + tid < NN) ? g_deg[base + tid] : 0;
        sh[tid] = v;
        __syncthreads();
        for (int off = 1; off < 1024; off <<= 1) {
            int t = (tid >= off) ? sh[tid - off] : 0;
            __syncthreads();
            sh[tid] += t;
            __syncthreads();
        }
        if (base + tid < NN) g_rowstart[base + tid] = carry + sh[tid] - v;
        int bs = sh[1023];
        __syncthreads();
        if (tid == 0) carry += bs;
        __syncthreads();
    }
    if (tid == 0) g_rowstart[NN] = carry;
}

__global__ void k_fill(const int* __restrict__ src, const int* __restrict__ dst, int E) {
    int e = blockIdx.x * blockDim.x + threadIdx.x;
    if (e >= E) return;
    int d = dst[e];
    int pos = atomicAdd(&g_cursor[d], 1);
    g_csr_src[g_rowstart[d] + pos] = src[e];
}

// ---------------- fused softmax + aggregation --------------------------------
// block per node (256 threads), warp per head, lane per output feature.
__global__ void k_aggr(float* __restrict__ out) {
    int n = blockIdx.x;
    int head = threadIdx.x >> 5;
    int lane = threadIdx.x & 31;
    __shared__ int s_rs, s_re;
    if (threadIdx.x == 0) {
        s_rs = g_rowstart[n];
        s_re = g_rowstart[n + 1];
    }
    __syncthreads();
    const int rs = s_rs, re = s_re;
    const float sd = g_sdst[n * HEADS_ + head];

    // phase 1: online softmax (max + sum) over incoming edges, lanes strided
    float m = -1e30f, ssum = 0.f;
    for (int i = rs + lane; i < re; i += 32) {
        int s = g_csr_src[i];
        float ea = g_ssrc[s * HEADS_ + head] + sd;
        ea = ea > 0.f ? ea : 0.2f * ea;
        if (ea > m) { ssum *= __expf(m - ea); m = ea; }
        ssum += __expf(ea - m);
    }
#pragma unroll
    for (int off = 16; off; off >>= 1) {
        float m2 = __shfl_xor_sync(0xffffffffu, m, off);
        float s2 = __shfl_xor_sync(0xffffffffu, ssum, off);
        float mn = fmaxf(m, m2);
        ssum = ssum * __expf(m - mn) + s2 * __expf(m2 - mn);
        m = mn;
    }
    float inv = 1.0f / (ssum + 1e-8f);

    // phase 2: weighted gather; coef recomputed per edge (broadcast loads),
    // each lane accumulates one output feature.
    float acc = 0.f;
    for (int i = rs; i < re; i++) {
        int s = g_csr_src[i];
        float ea = g_ssrc[s * HEADS_ + head] + sd;
        ea = ea > 0.f ? ea : 0.2f * ea;
        float c = __expf(ea - m) * inv;
        acc = fmaf(c, g_h[(size_t)s * HF_ + head * OUTF_ + lane], acc);
    }
    out[(size_t)n * HF_ + head * OUTF_ + lane] = acc;
}

// ---------------- launch -----------------------------------------------------
extern "C" void kernel_launch(void* const* d_in, const int* in_sizes, int n_in,
                              void* d_out, int out_size) {
    const float* x     = (const float*)d_in[0];
    const int*   ei    = (const int*)d_in[1];
    const float* W     = (const float*)d_in[2];
    const float* a_src = (const float*)d_in[3];
    const float* a_dst = (const float*)d_in[4];
    float* out = (float*)d_out;

    const int M = in_sizes[0] / INF_;     // 50000
    const int E = in_sizes[1] / 2;        // 800000
    const int* src = ei;
    const int* dst = ei + E;

    k_pack<<<(INF_ * HF_ + 255) / 256, 256>>>(W);
    k_gemm<<<dim3(HF_ / 64, (M + 127) / 128), 256>>>(x, M);
    k_scores<<<(M * HEADS_ + 255) / 256, 256>>>(a_src, a_dst, M);
    k_zero<<<(M + 255) / 256, 256>>>(M);
    k_count<<<(E + 255) / 256, 256>>>(dst, E);
    k_scan<<<1, 1024>>>(M);
    k_fill<<<(E + 255) / 256, 256>>>(src, dst, E);
    k_aggr<<<M, 256>>>(out);
}

// round 5
// speedup vs baseline: 1.0010x; 1.0004x over previous
#include <cuda_runtime.h>

#define N_NODES 50000
#define E_EDGES 800000
#define INF_    256
#define OUTF_   32
#define HEADS_  8
#define HF_     256   // HEADS_ * OUTF_

// ---------------- scratch (static __device__, no allocation) ----------------
__device__ float g_Wt[INF_ * HF_];                       // 256 KB packed weights [k][head*32+f]
__device__ float g_h[(size_t)N_NODES * HF_];             // 51.2 MB transformed features
__device__ float g_ssrc[N_NODES * HEADS_];               // 1.6 MB
__device__ float g_sdst[N_NODES * HEADS_];               // 1.6 MB
__device__ int   g_deg[N_NODES];
__device__ int   g_cursor[N_NODES];
__device__ int   g_rowstart[N_NODES + 1];
__device__ int   g_csr_src[E_EDGES];                     // 3.2 MB src per CSR slot

// ---------------- pack W [H,256,32] -> Wt [256, 256] ------------------------
__global__ void k_pack(const float* __restrict__ W) {
    int idx = blockIdx.x * blockDim.x + threadIdx.x;     // idx = k*256 + j
    if (idx >= INF_ * HF_) return;
    int k = idx >> 8;
    int j = idx & 255;
    int head = j >> 5;
    int f = j & 31;
    g_Wt[idx] = W[head * (INF_ * OUTF_) + k * OUTF_ + f];
}

// ---------------- GEMM: g_h[M,256] = x[M,256] @ g_Wt[256,256] ----------------
// BM=128, BN=64, BK=16, 256 threads, 8x4 micro-tile per thread.
__global__ void k_gemm(const float* __restrict__ x, int M) {
    __shared__ float As[16][128];
    __shared__ float Bs[16][64];
    const int tid = threadIdx.x;
    const int tx = tid & 15;        // col group (0..15) -> cols tx*4
    const int ty = tid >> 4;        // row group (0..15) -> rows ty*8
    const int n0 = blockIdx.x * 64;
    const int m0 = blockIdx.y * 128;

    float acc[8][4];
#pragma unroll
    for (int i = 0; i < 8; i++)
#pragma unroll
        for (int j = 0; j < 4; j++) acc[i][j] = 0.f;

    for (int k0 = 0; k0 < INF_; k0 += 16) {
        // load A tile 128x16 (transposed into As[k][m])
#pragma unroll
        for (int i = 0; i < 2; i++) {
            int id = tid + i * 256;          // 0..511 float4 slots
            int row = id >> 2;               // 0..127
            int c4 = id & 3;                 // 0..3
            float4 v = make_float4(0.f, 0.f, 0.f, 0.f);
            if (m0 + row < M)
                v = *(const float4*)&x[(size_t)(m0 + row) * INF_ + k0 + c4 * 4];
            As[c4 * 4 + 0][row] = v.x;
            As[c4 * 4 + 1][row] = v.y;
            As[c4 * 4 + 2][row] = v.z;
            As[c4 * 4 + 3][row] = v.w;
        }
        // load B tile 16x64
        {
            int row = tid >> 4;              // 0..15
            int c4 = tid & 15;               // 0..15
            *(float4*)&Bs[row][c4 * 4] =
                *(const float4*)&g_Wt[(k0 + row) * HF_ + n0 + c4 * 4];
        }
        __syncthreads();

#pragma unroll
        for (int k = 0; k < 16; k++) {
            float4 a0 = *(const float4*)&As[k][ty * 8];
            float4 a1 = *(const float4*)&As[k][ty * 8 + 4];
            float4 b = *(const float4*)&Bs[k][tx * 4];
            float av[8] = {a0.x, a0.y, a0.z, a0.w, a1.x, a1.y, a1.z, a1.w};
            float bv[4] = {b.x, b.y, b.z, b.w};
#pragma unroll
            for (int i = 0; i < 8; i++)
#pragma unroll
                for (int j = 0; j < 4; j++)
                    acc[i][j] = fmaf(av[i], bv[j], acc[i][j]);
        }
        __syncthreads();
    }

#pragma unroll
    for (int i = 0; i < 8; i++) {
        int row = m0 + ty * 8 + i;
        if (row < M) {
            float4 v = make_float4(acc[i][0], acc[i][1], acc[i][2], acc[i][3]);
            *(float4*)&g_h[(size_t)row * HF_ + n0 + tx * 4] = v;
        }
    }
}

// ---------------- per-(node,head) attention logits ---------------------------
__global__ void k_scores(const float* __restrict__ a_src,
                         const float* __restrict__ a_dst, int NN) {
    int t = blockIdx.x * blockDim.x + threadIdx.x;       // t = n*8 + head
    if (t >= NN * HEADS_) return;
    int n = t >> 3;
    int head = t & 7;
    const float4* hv = (const float4*)&g_h[(size_t)n * HF_ + head * OUTF_];
    const float4* sv = (const float4*)&a_src[head * OUTF_];
    const float4* dv = (const float4*)&a_dst[head * OUTF_];
    float ss = 0.f, sd = 0.f;
#pragma unroll
    for (int i = 0; i < 8; i++) {
        float4 h4 = hv[i], s4 = sv[i], d4 = dv[i];
        ss += h4.x * s4.x + h4.y * s4.y + h4.z * s4.z + h4.w * s4.w;
        sd += h4.x * d4.x + h4.y * d4.y + h4.z * d4.z + h4.w * d4.w;
    }
    g_ssrc[t] = ss;
    g_sdst[t] = sd;
}

// ---------------- CSR build --------------------------------------------------
__global__ void k_zero(int NN) {
    int t = blockIdx.x * blockDim.x + threadIdx.x;
    if (t < NN) { g_deg[t] = 0; g_cursor[t] = 0; }
}

__global__ void k_count(const int* __restrict__ dst, int E) {
    int e = blockIdx.x * blockDim.x + threadIdx.x;
    if (e < E) atomicAdd(&g_deg[dst[e]], 1);
}

__global__ void k_scan(int NN) {
    __shared__ int sh[1024];
    __shared__ int carry;
    int tid = threadIdx.x;
    if (tid == 0) carry = 0;
    __syncthreads();
    for (int base = 0; base < NN; base += 1024) {
        int v = (base + tid < NN) ? g_deg[base + tid] : 0;
        sh[tid] = v;
        __syncthreads();
        for (int off = 1; off < 1024; off <<= 1) {
            int t = (tid >= off) ? sh[tid - off] : 0;
            __syncthreads();
            sh[tid] += t;
            __syncthreads();
        }
        if (base + tid < NN) g_rowstart[base + tid] = carry + sh[tid] - v;
        int bs = sh[1023];
        __syncthreads();
        if (tid == 0) carry += bs;
        __syncthreads();
    }
    if (tid == 0) g_rowstart[NN] = carry;
}

__global__ void k_fill(const int* __restrict__ src, const int* __restrict__ dst, int E) {
    int e = blockIdx.x * blockDim.x + threadIdx.x;
    if (e >= E) return;
    int d = dst[e];
    int pos = atomicAdd(&g_cursor[d], 1);
    g_csr_src[g_rowstart[d] + pos] = src[e];
}

// ---------------- fused softmax + aggregation --------------------------------
// block per node (256 threads), warp per head, lane per output feature.
__global__ void k_aggr(float* __restrict__ out) {
    int n = blockIdx.x;
    int head = threadIdx.x >> 5;
    int lane = threadIdx.x & 31;
    __shared__ int s_rs, s_re;
    if (threadIdx.x == 0) {
        s_rs = g_rowstart[n];
        s_re = g_rowstart[n + 1];
    }
    __syncthreads();
    const int rs = s_rs, re = s_re;
    const float sd = g_sdst[n * HEADS_ + head];

    // phase 1: online softmax (max + sum) over incoming edges, lanes strided
    float m = -1e30f, ssum = 0.f;
    for (int i = rs + lane; i < re; i += 32) {
        int s = g_csr_src[i];
        float ea = g_ssrc[s * HEADS_ + head] + sd;
        ea = ea > 0.f ? ea : 0.2f * ea;
        if (ea > m) { ssum *= __expf(m - ea); m = ea; }
        ssum += __expf(ea - m);
    }
#pragma unroll
    for (int off = 16; off; off >>= 1) {
        float m2 = __shfl_xor_sync(0xffffffffu, m, off);
        float s2 = __shfl_xor_sync(0xffffffffu, ssum, off);
        float mn = fmaxf(m, m2);
        ssum = ssum * __expf(m - mn) + s2 * __expf(m2 - mn);
        m = mn;
    }
    float inv = 1.0f / (ssum + 1e-8f);

    // phase 2: weighted gather; coef recomputed per edge (broadcast loads),
    // each lane accumulates one output feature.
    float acc = 0.f;
    for (int i = rs; i < re; i++) {
        int s = g_csr_src[i];
        float ea = g_ssrc[s * HEADS_ + head] + sd;
        ea = ea > 0.f ? ea : 0.2f * ea;
        float c = __expf(ea - m) * inv;
        acc = fmaf(c, g_h[(size_t)s * HF_ + head * OUTF_ + lane], acc);
    }
    out[(size_t)n * HF_ + head * OUTF_ + lane] = acc;
}

// ---------------- launch -----------------------------------------------------
extern "C" void kernel_launch(void* const* d_in, const int* in_sizes, int n_in,
                              void* d_out, int out_size) {
    const float* x     = (const float*)d_in[0];
    const int*   ei    = (const int*)d_in[1];
    const float* W     = (const float*)d_in[2];
    const float* a_src = (const float*)d_in[3];
    const float* a_dst = (const float*)d_in[4];
    float* out = (float*)d_out;

    const int M = in_sizes[0] / INF_;     // 50000
    const int E = in_sizes[1] / 2;        // 800000
    const int* src = ei;
    const int* dst = ei + E;

    k_pack<<<(INF_ * HF_ + 255) / 256, 256>>>(W);
    k_gemm<<<dim3(HF_ / 64, (M + 127) / 128), 256>>>(x, M);
    k_scores<<<(M * HEADS_ + 255) / 256, 256>>>(a_src, a_dst, M);
    k_zero<<<(M + 255) / 256, 256>>>(M);
    k_count<<<(E + 255) / 256, 256>>>(dst, E);
    k_scan<<<1, 1024>>>(M);
    k_fill<<<(E + 255) / 256, 256>>>(src, dst, E);
    k_aggr<<<M, 256>>>(out);
}